// round 6
// baseline (speedup 1.0000x reference)
#include <cuda_runtime.h>
#include <cuda_bf16.h>
#include <cuda_fp16.h>
#include <cstdint>

#define NUM_ITER 10
#define MU_      (1.0f/256.0f)
#define EPS_     1e-8f
#define USCALE   4096.0f
#define MU_S     16.0f          /* MU_ * USCALE */
#define EPS_S    4.096e-5f      /* EPS_ * USCALE */
#define CEXP     (-28.853900817779268f)   /* -(1/tau)*log2(e) */
#define CLOG     (-0.034657359027997264f) /* -tau*ln(2) */

#define BSTR      272           /* bf16 B row stride (128 bf16 + pad) */
#define K8STR     272           /* fp8 K row stride (256 B + 16 pad) */
#define B_OFF     0             /* 69632 */
#define K8_OFF    69632         /* fp8 K row-major, 69632 */
#define KT8_OFF   139264        /* fp8 K^T, 69632 */
#define S2_OFF    208896
#define T2_OFF    209920
#define U_OFF     210944
#define V_OFF     211968
#define RED_OFF   212992
#define U8_OFF    213248        /* fp8 u*4096, 256B */
#define V8_OFF    213504        /* fp8 v, 256B */
#define SMEM_TOTAL 213760

__device__ __forceinline__ uint32_t smem_u32(const void* p) {
    uint32_t a;
    asm("{ .reg .u64 t; cvta.to.shared.u64 t, %1; cvt.u32.u64 %0, t; }" : "=r"(a) : "l"(p));
    return a;
}
__device__ __forceinline__ float fsqrt_ap(float x) { float r; asm("sqrt.approx.f32 %0, %1;" : "=f"(r) : "f"(x)); return r; }
__device__ __forceinline__ float fex2_ap (float x) { float r; asm("ex2.approx.f32 %0, %1;"  : "=f"(r) : "f"(x)); return r; }
__device__ __forceinline__ float flg2_ap (float x) { float r; asm("lg2.approx.f32 %0, %1;"  : "=f"(r) : "f"(x)); return r; }
__device__ __forceinline__ float frcp_ap (float x) { float r; asm("rcp.approx.f32 %0, %1;"  : "=f"(r) : "f"(x)); return r; }
__device__ __forceinline__ uint32_t b2u(__nv_bfloat162 h) { return *reinterpret_cast<uint32_t*>(&h); }
__device__ __forceinline__ uint32_t pack_bf(float a, float b) { return b2u(__floats2bfloat162_rn(a, b)); }
/* pack two f32 -> e4m3x2; first PTX source lands in the HIGH byte */
__device__ __forceinline__ unsigned short pack_e4m3(float lo, float hi) {
    unsigned short p;
    asm("cvt.rn.satfinite.e4m3x2.f32 %0, %1, %2;" : "=h"(p) : "f"(hi), "f"(lo));
    return p;
}
__device__ __forceinline__ float2 e4m3_to_f2(unsigned short p) {
    uint32_t h2;
    asm("cvt.rn.f16x2.e4m3x2 %0, %1;" : "=r"(h2) : "h"(p));
    return __half22float2(*reinterpret_cast<__half2*>(&h2));
}

/* bf16 m16n8k16 */
__device__ __forceinline__ void mma16816(float* c, const uint32_t* a, uint32_t b0, uint32_t b1) {
    asm volatile(
        "mma.sync.aligned.m16n8k16.row.col.f32.bf16.bf16.f32 "
        "{%0,%1,%2,%3}, {%4,%5,%6,%7}, {%8,%9}, {%0,%1,%2,%3};"
        : "+f"(c[0]), "+f"(c[1]), "+f"(c[2]), "+f"(c[3])
        : "r"(a[0]), "r"(a[1]), "r"(a[2]), "r"(a[3]), "r"(b0), "r"(b1));
}
/* e4m3 m16n8k32 */
__device__ __forceinline__ void mma_fp8(float* c, const uint32_t* a, uint32_t b0, uint32_t b1) {
    asm volatile(
        "mma.sync.aligned.m16n8k32.row.col.f32.e4m3.e4m3.f32 "
        "{%0,%1,%2,%3}, {%4,%5,%6,%7}, {%8,%9}, {%0,%1,%2,%3};"
        : "+f"(c[0]), "+f"(c[1]), "+f"(c[2]), "+f"(c[3])
        : "r"(a[0]), "r"(a[1]), "r"(a[2]), "r"(a[3]), "r"(b0), "r"(b1));
}
__device__ __forceinline__ void ldsm4(uint32_t* r, uint32_t addr) {
    asm volatile("ldmatrix.sync.aligned.m8n8.x4.shared.b16 {%0,%1,%2,%3}, [%4];"
        : "=r"(r[0]), "=r"(r[1]), "=r"(r[2]), "=r"(r[3]) : "r"(addr));
}

__device__ float g_partial[1024];
__device__ int   g_count = 0;

__global__ void __launch_bounds__(512, 1)
sinkhorn_kernel(const float* __restrict__ src, const float* __restrict__ tgt,
                float* __restrict__ out) {
    extern __shared__ char sm[];
    const int tid = threadIdx.x, wid = tid >> 5, lane = tid & 31;
    const int g = lane >> 2, t = lane & 3;
    const int bt = blockIdx.x;

    float* s2arr = (float*)(sm + S2_OFF);
    float* t2arr = (float*)(sm + T2_OFF);
    float* uarr  = (float*)(sm + U_OFF);
    float* varr  = (float*)(sm + V_OFF);
    float* red   = (float*)(sm + RED_OFF);
    char*  u8c   = sm + U8_OFF;
    char*  v8c   = sm + V8_OFF;

    /* ---- phase 1a: tgt -> smem bf16 [n][k]; t2 row sums ---- */
    {
        const float4* t4 = reinterpret_cast<const float4*>(tgt) + (size_t)bt * 8192;
        #pragma unroll 4
        for (int j = 0; j < 16; j++) {
            int row = 16 * j + wid;
            float4 f = t4[row * 32 + lane];
            float ss = f.x*f.x + f.y*f.y + f.z*f.z + f.w*f.w;
            #pragma unroll
            for (int o = 16; o > 0; o >>= 1) ss += __shfl_xor_sync(0xffffffffu, ss, o);
            if (lane == 0) t2arr[row] = ss;
            *reinterpret_cast<uint2*>(sm + B_OFF + row * BSTR + lane * 8) =
                make_uint2(pack_bf(f.x, f.y), pack_bf(f.z, f.w));
        }
    }

    /* ---- phase 1b: src -> A fragments, 32-row strip per warp (wm = wid&7) ---- */
    const int wm = wid & 7, wn = wid >> 3;
    uint32_t afrag[2][8][4];
    {
        const float2* a2 = reinterpret_cast<const float2*>(src) + (size_t)bt * 16384;
        #pragma unroll
        for (int mt = 0; mt < 2; mt++) {
            const int r0 = 32 * wm + 16 * mt + g, r1 = r0 + 8;
            float s0 = 0.0f, s1 = 0.0f;
            #pragma unroll
            for (int ks = 0; ks < 8; ks++) {
                int kk = 8 * ks + t;
                float2 f00 = a2[r0 * 64 + kk];
                float2 f10 = a2[r1 * 64 + kk];
                float2 f01 = a2[r0 * 64 + kk + 4];
                float2 f11 = a2[r1 * 64 + kk + 4];
                afrag[mt][ks][0] = pack_bf(f00.x, f00.y);
                afrag[mt][ks][1] = pack_bf(f10.x, f10.y);
                afrag[mt][ks][2] = pack_bf(f01.x, f01.y);
                afrag[mt][ks][3] = pack_bf(f11.x, f11.y);
                s0 += f00.x*f00.x + f00.y*f00.y + f01.x*f01.x + f01.y*f01.y;
                s1 += f10.x*f10.x + f10.y*f10.y + f11.x*f11.x + f11.y*f11.y;
            }
            s0 += __shfl_xor_sync(0xffffffffu, s0, 1); s0 += __shfl_xor_sync(0xffffffffu, s0, 2);
            s1 += __shfl_xor_sync(0xffffffffu, s1, 1); s1 += __shfl_xor_sync(0xffffffffu, s1, 2);
            if (t == 0) { s2arr[r0] = s0; s2arr[r1] = s1; }   /* wn-duplicate: same bits */
        }
    }
    if (tid < 256) { v8c[tid] = (char)0x38; }                 /* e4m3(1.0) */
    __syncthreads();

    /* ---- phase 2: HMMA GEMM (8x2 warp tiling) -> K fp8 + K^T fp8 ---- */
    {
        const int r0 = 32 * wm + g;
        const float s20 = s2arr[r0], s21 = s2arr[r0 + 8];
        const float s22 = s2arr[r0 + 16], s23 = s2arr[r0 + 24];
        char* k8  = sm + K8_OFF;
        char* kt8 = sm + KT8_OFF;
        #pragma unroll 2
        for (int j = 0; j < 16; j++) {
            const int cb = 128 * wn + 8 * j;
            const char* bp = sm + B_OFF + (cb + g) * BSTR + 4 * t;
            float acc0[4] = {0.f, 0.f, 0.f, 0.f};
            float acc1[4] = {0.f, 0.f, 0.f, 0.f};
            #pragma unroll
            for (int ks = 0; ks < 8; ks++) {
                uint32_t b0 = *reinterpret_cast<const uint32_t*>(bp + 32 * ks);
                uint32_t b1 = *reinterpret_cast<const uint32_t*>(bp + 32 * ks + 16);
                mma16816(acc0, afrag[0][ks], b0, b1);
                mma16816(acc1, afrag[1][ks], b0, b1);
            }
            const int c0 = cb + 2 * t;
            const float t20 = t2arr[c0], t21 = t2arr[c0 + 1];
            float x0, x1, k0, k1;
            unsigned short p;
            x0 = fmaxf(s20 + t20 - 2.0f * acc0[0], 0.0f); k0 = fex2_ap(fsqrt_ap(x0) * CEXP);
            x1 = fmaxf(s20 + t21 - 2.0f * acc0[1], 0.0f); k1 = fex2_ap(fsqrt_ap(x1) * CEXP);
            p = pack_e4m3(k0, k1);
            *(unsigned short*)(k8 + r0 * K8STR + c0) = p;
            kt8[c0 * K8STR + r0] = (char)(p & 0xff);
            kt8[(c0 + 1) * K8STR + r0] = (char)(p >> 8);
            x0 = fmaxf(s21 + t20 - 2.0f * acc0[2], 0.0f); k0 = fex2_ap(fsqrt_ap(x0) * CEXP);
            x1 = fmaxf(s21 + t21 - 2.0f * acc0[3], 0.0f); k1 = fex2_ap(fsqrt_ap(x1) * CEXP);
            p = pack_e4m3(k0, k1);
            *(unsigned short*)(k8 + (r0 + 8) * K8STR + c0) = p;
            kt8[c0 * K8STR + r0 + 8] = (char)(p & 0xff);
            kt8[(c0 + 1) * K8STR + r0 + 8] = (char)(p >> 8);
            x0 = fmaxf(s22 + t20 - 2.0f * acc1[0], 0.0f); k0 = fex2_ap(fsqrt_ap(x0) * CEXP);
            x1 = fmaxf(s22 + t21 - 2.0f * acc1[1], 0.0f); k1 = fex2_ap(fsqrt_ap(x1) * CEXP);
            p = pack_e4m3(k0, k1);
            *(unsigned short*)(k8 + (r0 + 16) * K8STR + c0) = p;
            kt8[c0 * K8STR + r0 + 16] = (char)(p & 0xff);
            kt8[(c0 + 1) * K8STR + r0 + 16] = (char)(p >> 8);
            x0 = fmaxf(s23 + t20 - 2.0f * acc1[2], 0.0f); k0 = fex2_ap(fsqrt_ap(x0) * CEXP);
            x1 = fmaxf(s23 + t21 - 2.0f * acc1[3], 0.0f); k1 = fex2_ap(fsqrt_ap(x1) * CEXP);
            p = pack_e4m3(k0, k1);
            *(unsigned short*)(k8 + (r0 + 24) * K8STR + c0) = p;
            kt8[c0 * K8STR + r0 + 24] = (char)(p & 0xff);
            kt8[(c0 + 1) * K8STR + r0 + 24] = (char)(p >> 8);
        }
    }
    __syncthreads();

    /* ---- phase 3: 10 Sinkhorn iterations, fp8 HMMA matvecs ---- */
    {
        const int l7 = lane & 7, q = lane >> 3;
        const uint32_t rowsel = (16 * wid + l7 + (q & 1) * 8) * K8STR + (q >> 1) * 16;
        const uint32_t ua8 = smem_u32(sm + K8_OFF) + rowsel;
        const uint32_t va8 = smem_u32(sm + KT8_OFF) + rowsel;
        const uint32_t* u8w = (const uint32_t*)(sm + U8_OFF);
        const uint32_t* v8w = (const uint32_t*)(sm + V8_OFF);

        for (int it = 0; it < NUM_ITER; it++) {
            /* u = mu / (K v + eps) */
            float acc[4] = {0.f, 0.f, 0.f, 0.f};
            #pragma unroll
            for (int s = 0; s < 8; s++) {
                uint32_t a[4];
                ldsm4(a, ua8 + 32 * s);
                mma_fp8(acc, a, v8w[8 * s + t], v8w[8 * s + 4 + t]);
            }
            if (t == 0) {
                int r = 16 * wid + g;
                float u0 = MU_ * frcp_ap(acc[0] + EPS_);
                float u1 = MU_ * frcp_ap(acc[2] + EPS_);
                uarr[r] = u0; uarr[r + 8] = u1;
                u8c[r]     = (char)(pack_e4m3(u0 * USCALE, 0.f) & 0xff);
                u8c[r + 8] = (char)(pack_e4m3(u1 * USCALE, 0.f) & 0xff);
            }
            __syncthreads();
            /* v = mu / (K^T u + eps); operand is u*4096, algebra folded into MU_S/EPS_S */
            float c[4] = {0.f, 0.f, 0.f, 0.f};
            #pragma unroll
            for (int s = 0; s < 8; s++) {
                uint32_t a[4];
                ldsm4(a, va8 + 32 * s);
                mma_fp8(c, a, u8w[8 * s + t], u8w[8 * s + 4 + t]);
            }
            if (t == 0) {
                int m = 16 * wid + g;
                float v0 = MU_S * frcp_ap(c[0] + EPS_S);
                float v1 = MU_S * frcp_ap(c[2] + EPS_S);
                varr[m] = v0; varr[m + 8] = v1;
                v8c[m]     = (char)(pack_e4m3(v0, 0.f) & 0xff);
                v8c[m + 8] = (char)(pack_e4m3(v1, 0.f) & 0xff);
            }
            __syncthreads();
        }
    }

    /* ---- phase 4: loss = sum u K v cost, cost = CLOG * log2(K) ---- */
    {
        const int row = tid >> 1, half = tid & 1;
        const uint4* kr4 = reinterpret_cast<const uint4*>(sm + K8_OFF + row * K8STR + half * 128);
        const float* vv = varr + half * 128;
        float acc = 0.0f;
        #pragma unroll
        for (int j = 0; j < 8; j++) {
            uint4 q4 = kr4[j];
            uint32_t ws[4] = {q4.x, q4.y, q4.z, q4.w};
            #pragma unroll
            for (int i = 0; i < 4; i++) {
                float2 f0 = e4m3_to_f2((unsigned short)(ws[i] & 0xffff));
                float2 f1 = e4m3_to_f2((unsigned short)(ws[i] >> 16));
                int vb = 16 * j + 4 * i;
                acc += f0.x * vv[vb]     * flg2_ap(fmaxf(f0.x, 1e-30f));
                acc += f0.y * vv[vb + 1] * flg2_ap(fmaxf(f0.y, 1e-30f));
                acc += f1.x * vv[vb + 2] * flg2_ap(fmaxf(f1.x, 1e-30f));
                acc += f1.y * vv[vb + 3] * flg2_ap(fmaxf(f1.y, 1e-30f));
            }
        }
        acc *= uarr[row] * CLOG;
        #pragma unroll
        for (int o = 16; o > 0; o >>= 1) acc += __shfl_xor_sync(0xffffffffu, acc, o);
        if (lane == 0) red[wid] = acc;
        __syncthreads();
        if (tid == 0) {
            float tsum = 0.0f;
            #pragma unroll
            for (int w = 0; w < 16; w++) tsum += red[w];
            g_partial[bt] = tsum;
        }
    }

    /* ---- phase 5: last block reduces g_partial -> out ---- */
    __shared__ int is_last;
    if (tid == 0) {
        __threadfence();
        int c = atomicAdd(&g_count, 1);
        is_last = (c == 1023);
    }
    __syncthreads();
    if (is_last) {
        if (tid == 0) g_count = 0;
        float s = g_partial[tid] + g_partial[tid + 512];
        #pragma unroll
        for (int o = 16; o > 0; o >>= 1) s += __shfl_xor_sync(0xffffffffu, s, o);
        if (lane == 0) red[wid] = s;
        __syncthreads();
        if (tid == 0) {
            float tsum = 0.0f;
            #pragma unroll
            for (int w = 0; w < 16; w++) tsum += red[w];
            out[0] = tsum * (1.0f / 1024.0f);
        }
    }
}

extern "C" void kernel_launch(void* const* d_in, const int* in_sizes, int n_in,
                              void* d_out, int out_size) {
    const float* src = (const float*)d_in[0];
    const float* tgt = (const float*)d_in[1];
    float* out = (float*)d_out;
    cudaFuncSetAttribute(sinkhorn_kernel, cudaFuncAttributeMaxDynamicSharedMemorySize, SMEM_TOTAL);
    sinkhorn_kernel<<<1024, 512, SMEM_TOTAL>>>(src, tgt, out);
}